// round 1
// baseline (speedup 1.0000x reference)
#include <cuda_runtime.h>

// Depthwise conv_transpose2d(stride=4, k=7) == separable x4 bilinear upsample.
// Input  x: [4, 256, 64, 64]  fp32  (d_in[0])
// Weight : [256, 1, 7, 7]     fp32  (d_in[1]) -- fixed bilinear kernel,
//          outer(w,w) with w = [.25,.5,.75,1,.75,.5,.25]; hardcoded below.
// Output : [4, 256, 259, 259] fp32
//
// Tap algebra (derived from lhs_dilation=4, pad=6, k=7):
//   oy = 4a + p, p in 0..3:
//     p=0: 0.75*row[a-1] + 0.25*row[a]
//     p=1: 0.50*row[a-1] + 0.50*row[a]
//     p=2: 0.25*row[a-1] + 0.75*row[a]
//     p=3:                 1.00*row[a]
//   (identical decomposition along x with columns {b-1, b})
// Out-of-range taps contribute zero (matches implicit zero padding).

namespace {
constexpr int N  = 4;
constexpr int C  = 256;
constexpr int H  = 64;
constexpr int W  = 64;
constexpr int OH = 259;
constexpr int OW = 259;
constexpr int AB = 65;                         // 4-row output blocks per plane (ceil(259/4))
constexpr int PLANES = N * C;                  // 1024
constexpr int TOTAL  = PLANES * AB * OW;       // 17,239,040 threads
constexpr int THREADS = 256;
}

__global__ void __launch_bounds__(THREADS)
bilinear_up4_kernel(const float* __restrict__ x, float* __restrict__ out) {
    int t = blockIdx.x * THREADS + threadIdx.x;
    if (t >= TOTAL) return;

    int ox    = t % OW;
    int rest  = t / OW;
    int a     = rest % AB;        // y-block index: output rows [4a, 4a+3]
    int plane = rest / AB;        // n*C + c

    const float* __restrict__ xp = x + (size_t)plane * (H * W);
    float* __restrict__ op = out + (size_t)plane * ((size_t)OH * OW);

    // --- horizontal taps ---
    int b  = ox >> 2;
    int px = ox & 3;
    float wxA, wxB;
    int cA, cB;
    if (px == 3) {
        cA = b; cB = -1; wxA = 1.0f; wxB = 0.0f;
    } else {
        cA = b - 1; cB = b;
        wxA = 0.75f - 0.25f * (float)px;   // 0.75, 0.50, 0.25
        wxB = 1.0f - wxA;
    }
    bool cAok = (cA >= 0);                 // cA <= 63 always
    bool cBok = (cB >= 0) && (cB < W);     // cB == 64 possible at ox=258

    // --- vertical taps: rows a-1 and a ---
    int  rA   = a - 1;
    bool rAok = (rA >= 0);                 // rA <= 63 always
    bool rBok = (a < H);                   // a == 64 possible (last partial block)

    const float* rowA = xp + rA * W;
    const float* rowB = xp + a  * W;

    float vAA = (rAok && cAok) ? __ldg(rowA + cA) : 0.0f;
    float vAB = (rAok && cBok) ? __ldg(rowA + cB) : 0.0f;
    float vBA = (rBok && cAok) ? __ldg(rowB + cA) : 0.0f;
    float vBB = (rBok && cBok) ? __ldg(rowB + cB) : 0.0f;

    // horizontal blends for the two contributing input rows
    float hA = vAA * wxA + vAB * wxB;      // from input row a-1
    float hB = vBA * wxA + vBB * wxB;      // from input row a

    // vertical blends -> 4 output rows (coalesced stores across the warp)
    int oy0 = 4 * a;
    float* o0 = op + (size_t)oy0 * OW + ox;
    o0[0]      = 0.75f * hA + 0.25f * hB;
    o0[OW]     = 0.50f * hA + 0.50f * hB;
    o0[2 * OW] = 0.25f * hA + 0.75f * hB;
    if (oy0 + 3 < OH)
        o0[3 * OW] = hB;                   // center row: identity at stride points
}

extern "C" void kernel_launch(void* const* d_in, const int* in_sizes, int n_in,
                              void* d_out, int out_size) {
    const float* x = (const float*)d_in[0];
    float* out = (float*)d_out;
    (void)in_sizes; (void)n_in; (void)out_size;

    int blocks = (TOTAL + THREADS - 1) / THREADS;   // 67,340
    bilinear_up4_kernel<<<blocks, THREADS>>>(x, out);
}